// round 15
// baseline (speedup 1.0000x reference)
#include <cuda_runtime.h>
#include <cuda_fp16.h>
#include <cstdint>
#include <cstddef>

#define NN   25000
#define EE   50000
#define EE3  40000
#define DIM  64

// Wedge stored as e4m3 scaled by 32 (decoded value = stored/32)
#define WSCALE     32.0f
#define WSCALE_INV 0.03125f
// fp8 GEMM input scales: hr*16, W2*32 -> acc scale 512; output = acc/512*WSCALE
#define HR_SCALE   16.0f
#define W2_SCALE   32.0f
#define OUT_SCALE  0.0625f   // WSCALE / (HR_SCALE*W2_SCALE)

// ---------------- scratch (device globals; no allocation at launch time) ----
__device__ float   g_h[NN * DIM];                      // node features / GRU state
__device__ float   g_agg[NN * DIM];                    // scatter-sum accumulator
__device__ uint8_t g_hr8[EE * 128];                    // edge hidden (e4m3 * 16)
__device__ uint8_t g_W2T8[4096 * 128];                 // W_e2^T (e4m3 * 32) [col][k]
__device__ uint8_t g_Wedge8[(size_t)EE * DIM * DIM];   // 205 MB per-edge weights (e4m3*32)
__device__ float   g_cnt[NN];
__device__ float   g_invcnt[NN];
__device__ __half  g_WcatT[256 * 128];                 // GRU gate weights [gate][k]
__device__ float   g_gates[(size_t)NN * 256];          // GEMM gate outputs

// ---------------- helpers -----------------------------------------------------
__device__ __forceinline__ uint32_t smem_to_u32(const void* p) {
    uint32_t a;
    asm("{ .reg .u64 t; cvta.to.shared.u64 t, %1; cvt.u32.u64 %0, t; }"
        : "=r"(a) : "l"(p));
    return a;
}
__device__ __forceinline__ void ldsm4(uint32_t* r, uint32_t addr) {
    asm volatile("ldmatrix.sync.aligned.m8n8.x4.shared.b16 {%0,%1,%2,%3}, [%4];"
                 : "=r"(r[0]), "=r"(r[1]), "=r"(r[2]), "=r"(r[3]) : "r"(addr));
}
// fp32-accumulate HMMA (full rate on sm_103; fp16-acc measured SLOWER)
__device__ __forceinline__ void mma16816(float* d, const uint32_t* a,
                                         const uint32_t* b) {
    asm volatile(
        "mma.sync.aligned.m16n8k16.row.col.f32.f16.f16.f32 "
        "{%0,%1,%2,%3}, {%4,%5,%6,%7}, {%8,%9}, {%0,%1,%2,%3};"
        : "+f"(d[0]), "+f"(d[1]), "+f"(d[2]), "+f"(d[3])
        : "r"(a[0]), "r"(a[1]), "r"(a[2]), "r"(a[3]), "r"(b[0]), "r"(b[1]));
}
// fp8 e4m3 MMA, k32: fragment bytes identical to fp16 k16 -> same ldsm pattern
__device__ __forceinline__ void mma16832f8(float* d, const uint32_t* a,
                                           const uint32_t* b) {
    asm volatile(
        "mma.sync.aligned.m16n8k32.row.col.f32.e4m3.e4m3.f32 "
        "{%0,%1,%2,%3}, {%4,%5,%6,%7}, {%8,%9}, {%0,%1,%2,%3};"
        : "+f"(d[0]), "+f"(d[1]), "+f"(d[2]), "+f"(d[3])
        : "r"(a[0]), "r"(a[1]), "r"(a[2]), "r"(a[3]), "r"(b[0]), "r"(b[1]));
}
__device__ __forceinline__ uint16_t f32x2_to_e4m3(float lo, float hi) {
    uint16_t r;
    asm("cvt.rn.satfinite.e4m3x2.f32 %0, %1, %2;" : "=h"(r) : "f"(hi), "f"(lo));
    return r;
}
__device__ __forceinline__ uint32_t e4m3x2_to_f16x2(uint16_t v) {
    uint32_t r;
    asm("cvt.rn.f16x2.e4m3x2 %0, %1;" : "=r"(r) : "h"(v));
    return r;
}

// ---------------- fused prep: node MLP + zero agg + zero cnt ------------------
__global__ void prep_kernel(const float* __restrict__ x,
                            const float* __restrict__ Wn,
                            const float* __restrict__ bn, int N) {
    int i = blockIdx.x * 256 + threadIdx.x;
    if (i < N) g_cnt[i] = 0.f;
    if (i >= N * DIM) return;
    g_agg[i] = 0.f;
    int n = i >> 6, f = i & 63;
    float acc = bn[f];
#pragma unroll
    for (int k = 0; k < 8; k++) acc += x[n * 8 + k] * Wn[k * DIM + f];
    g_h[i] = fmaxf(acc, 0.f);
}

__global__ void invcnt_kernel(int N) {
    int i = blockIdx.x * 256 + threadIdx.x;
    if (i < N) g_invcnt[i] = 1.f / fmaxf(g_cnt[i], 1.f);
}

// build WcatT[256][128]: rows 0-63 [Wih_r|Whh_r], 64-127 [Wih_z|Whh_z],
// 128-191 [Wih_n|0], 192-255 [0|Whh_n]
__global__ void wcat_kernel(const float* __restrict__ W_ih,
                            const float* __restrict__ W_hh) {
    int i = blockIdx.x * 256 + threadIdx.x;
    if (i >= 256 * 128) return;
    int g = i >> 7, k = i & 127;
    float v;
    if (g < 128)      v = (k < 64) ? W_ih[g * 64 + k] : W_hh[g * 64 + (k - 64)];
    else if (g < 192) v = (k < 64) ? W_ih[g * 64 + k] : 0.f;
    else              v = (k >= 64) ? W_hh[(g - 64) * 64 + (k - 64)] : 0.f;
    g_WcatT[g * 128 + k] = __float2half(v);
}

// -------- fused edge MLP (8 edges/block) + degree count + W_e2 transpose ------
#define EDGES_PER_BLK 8
__global__ void __launch_bounds__(128) edge_w2t_kernel(
    const float* __restrict__ ea_in, const float* __restrict__ W_ea,
    const float* __restrict__ b_ea, const float* __restrict__ W_e1,
    const float* __restrict__ b_e1, const float* __restrict__ W2,
    const int* __restrict__ dst, int E) {
    int tid = threadIdx.x;
    int EB = (E + EDGES_PER_BLK - 1) / EDGES_PER_BLK;
    if ((int)blockIdx.x >= EB) {
        int i = ((int)blockIdx.x - EB) * 128 + tid;
        int n = i & 4095, k = i >> 12;
        g_W2T8[(size_t)n * 128 + k] =
            (uint8_t)f32x2_to_e4m3(W2[(size_t)k * 4096 + n] * W2_SCALE, 0.f);
        return;
    }
    __shared__ float row[EDGES_PER_BLK][20];   // padded
    __shared__ float eah[EDGES_PER_BLK][12];
    int e0 = blockIdx.x * EDGES_PER_BLK;
    int ecnt = min(EDGES_PER_BLK, E - e0);
    for (int i = tid; i < ecnt * 19; i += 128)
        row[i / 19][i % 19] = ea_in[(size_t)e0 * 19 + i];
    if (tid < ecnt) atomicAdd(&g_cnt[dst[e0 + tid]], 1.f);
    __syncthreads();
    if (tid < ecnt * 12) {
        int el = tid / 12, j = tid % 12;
        float a = b_ea[j];
#pragma unroll
        for (int i = 0; i < 19; i++) a += row[el][i] * W_ea[i * 12 + j];
        eah[el][j] = fmaxf(a, 0.f);
    }
    __syncthreads();
    float w[12];
#pragma unroll
    for (int k = 0; k < 12; k++) w[k] = W_e1[k * 128 + tid];
    float be = b_e1[tid];
#pragma unroll
    for (int el = 0; el < EDGES_PER_BLK; el++) {
        if (el >= ecnt) break;
        float a = be;
#pragma unroll
        for (int k = 0; k < 12; k++) a += eah[el][k] * w[k];
        g_hr8[(size_t)(e0 + el) * 128 + tid] =
            (uint8_t)f32x2_to_e4m3(fmaxf(a, 0.f) * HR_SCALE, 0.f);
    }
}

// ============ fp8 HMMA Wedge GEMM (e4m3 in, fp32 acc, e4m3*32 out) ===========
// R6 skeleton, fp8 operands: 4 x k32 steps, half the LDSM traffic & MMA count.
// Byte row stride 144 (144 mod 128 = 16 -> conflict-free ldsm).
#define F8STRIDE 144
#define A8_OFF   0
#define B8_OFF   (128 * F8STRIDE)            // 18432
#define BIAS8_OFF (2 * 128 * F8STRIDE)       // 36864
#define WM_SMEM_SIZE (BIAS8_OFF + 128 * 4)   // 37376
#define CBSTR 144   // byte stride of fp8 staging rows (16-aligned)

__global__ void __launch_bounds__(256) wedge_mma_kernel(
    const float* __restrict__ b2, int E) {
    extern __shared__ char smem[];
    uint8_t* As = (uint8_t*)(smem + A8_OFF);
    uint8_t* Bs = (uint8_t*)(smem + B8_OFF);
    float* sbias = (float*)(smem + BIAS8_OFF);
    uint32_t sbase = smem_to_u32(smem);
    int tid = threadIdx.x;
    int ebase = blockIdx.x * 128;
    int colbase = blockIdx.y * 128;

    if (tid < 128) sbias[tid] = b2[colbase + tid] * WSCALE;

    // A tile: 128 rows x 128 bytes (8 uint4 per row)
#pragma unroll
    for (int it = 0; it < 4; it++) {
        int idx = it * 256 + tid;
        int r = idx >> 3, c = idx & 7;
        uint4 v = make_uint4(0, 0, 0, 0);
        if (ebase + r < E)
            v = *(const uint4*)(g_hr8 + ((size_t)(ebase + r) << 7) + c * 16);
        *(uint4*)(As + r * F8STRIDE + c * 16) = v;
    }
    // B tile: 128 n-rows x 128 bytes
#pragma unroll
    for (int it = 0; it < 4; it++) {
        int idx = it * 256 + tid;
        int r = idx >> 3, c = idx & 7;
        uint4 v = *(const uint4*)(g_W2T8 + ((size_t)(colbase + r) << 7) + c * 16);
        *(uint4*)(Bs + r * F8STRIDE + c * 16) = v;
    }
    __syncthreads();

    int w = tid >> 5, lane = tid & 31;
    int wm = (w & 3) * 32;
    int wn = (w >> 2) * 64;

    float acc[2][8][4];
#pragma unroll
    for (int i = 0; i < 2; i++)
#pragma unroll
        for (int j = 0; j < 8; j++)
#pragma unroll
            for (int q = 0; q < 4; q++) acc[i][j][q] = 0.f;

    uint32_t a_addr[2];
#pragma unroll
    for (int i = 0; i < 2; i++)
        a_addr[i] = sbase + A8_OFF +
                    (uint32_t)((wm + i * 16 + (lane & 15)) * F8STRIDE +
                               (lane >> 4) * 16);
    uint32_t b_addr[4];
#pragma unroll
    for (int jj = 0; jj < 4; jj++)
        b_addr[jj] = sbase + B8_OFF +
                     (uint32_t)((wn + jj * 16 + ((lane >> 4) & 1) * 8 + (lane & 7)) *
                                    F8STRIDE +
                                ((lane >> 3) & 1) * 16);

#pragma unroll
    for (int s = 0; s < 4; s++) {
        uint32_t a[2][4], b[4][4];
#pragma unroll
        for (int i = 0; i < 2; i++) ldsm4(a[i], a_addr[i] + s * 32);
#pragma unroll
        for (int jj = 0; jj < 4; jj++) ldsm4(b[jj], b_addr[jj] + s * 32);
#pragma unroll
        for (int i = 0; i < 2; i++)
#pragma unroll
            for (int jj = 0; jj < 4; jj++) {
                mma16832f8(acc[i][2 * jj], a[i], &b[jj][0]);
                mma16832f8(acc[i][2 * jj + 1], a[i], &b[jj][2]);
            }
    }
    __syncthreads();   // reuse smem as fp8 staging

    uint8_t* Cs = (uint8_t*)smem;
    int g = lane >> 2, tg = lane & 3;
#pragma unroll
    for (int i = 0; i < 2; i++) {
#pragma unroll
        for (int j = 0; j < 8; j++) {
            int col = wn + j * 8 + tg * 2;
            float b0 = sbias[col], b1 = sbias[col + 1];
            int r0 = wm + i * 16 + g;
            uint16_t p0 = f32x2_to_e4m3(acc[i][j][0] * OUT_SCALE + b0,
                                        acc[i][j][1] * OUT_SCALE + b1);
            uint16_t p1 = f32x2_to_e4m3(acc[i][j][2] * OUT_SCALE + b0,
                                        acc[i][j][3] * OUT_SCALE + b1);
            *(uint16_t*)(Cs + r0 * CBSTR + col) = p0;
            *(uint16_t*)(Cs + (r0 + 8) * CBSTR + col) = p1;
        }
    }
    __syncthreads();

#pragma unroll
    for (int it = 0; it < 4; it++) {
        int idx = it * 256 + tid;
        int r = idx >> 3, c = idx & 7;
        if (ebase + r < E) {
            uint4 v = *(const uint4*)(Cs + r * CBSTR + c * 16);
            *(uint4*)(g_Wedge8 + (size_t)(ebase + r) * 4096 + colbase + c * 16) = v;
        }
    }
}

// ============ HMMA GRU gate GEMM (m computed in A-load) ======================
#define WSTRIDE 136
#define AS_OFF  0
#define BS_OFF  (128 * WSTRIDE * 2)
#define GM_SMEM_SIZE (2 * 128 * WSTRIDE * 2)
#define CFSTR 132   // float stride of fp32 staging rows

__global__ void __launch_bounds__(256) gru_mma_kernel(
    const float* __restrict__ conv_bias, int N) {
    extern __shared__ char smem[];
    __half* As = (__half*)(smem + AS_OFF);
    __half* Bs = (__half*)(smem + BS_OFF);
    uint32_t sbase = smem_to_u32(smem);
    int tid = threadIdx.x;
    int nb = blockIdx.x * 128;
    int colbase = blockIdx.y * 128;

    // A: build fp16 [m|h] tile from fp32 agg/h (chunks c<8 -> m, c>=8 -> h)
#pragma unroll
    for (int it = 0; it < 8; it++) {
        int idx = it * 256 + tid;
        int r = idx >> 4, c = idx & 15;
        int n = nb + r;
        uint4 o = make_uint4(0, 0, 0, 0);
        if (n < N) {
            int f0 = (c & 7) * 8;
            float4 v0, v1;
            if (c < 8) {
                v0 = *(const float4*)(g_agg + (size_t)n * 64 + f0);
                v1 = *(const float4*)(g_agg + (size_t)n * 64 + f0 + 4);
                float ic = g_invcnt[n];
                float4 cb0 = *(const float4*)(conv_bias + f0);
                float4 cb1 = *(const float4*)(conv_bias + f0 + 4);
                v0.x = fmaxf(v0.x * ic + cb0.x, 0.f);
                v0.y = fmaxf(v0.y * ic + cb0.y, 0.f);
                v0.z = fmaxf(v0.z * ic + cb0.z, 0.f);
                v0.w = fmaxf(v0.w * ic + cb0.w, 0.f);
                v1.x = fmaxf(v1.x * ic + cb1.x, 0.f);
                v1.y = fmaxf(v1.y * ic + cb1.y, 0.f);
                v1.z = fmaxf(v1.z * ic + cb1.z, 0.f);
                v1.w = fmaxf(v1.w * ic + cb1.w, 0.f);
            } else {
                v0 = *(const float4*)(g_h + (size_t)n * 64 + f0);
                v1 = *(const float4*)(g_h + (size_t)n * 64 + f0 + 4);
            }
            __half2 h0 = __floats2half2_rn(v0.x, v0.y);
            __half2 h1 = __floats2half2_rn(v0.z, v0.w);
            __half2 h2 = __floats2half2_rn(v1.x, v1.y);
            __half2 h3 = __floats2half2_rn(v1.z, v1.w);
            o.x = *(uint32_t*)&h0; o.y = *(uint32_t*)&h1;
            o.z = *(uint32_t*)&h2; o.w = *(uint32_t*)&h3;
        }
        *(uint4*)(As + r * WSTRIDE + c * 8) = o;
    }
#pragma unroll
    for (int it = 0; it < 8; it++) {
        int idx = it * 256 + tid;
        int r = idx >> 4, c = idx & 15;
        uint4 v = *(const uint4*)(g_WcatT + ((size_t)(colbase + r) << 7) + c * 8);
        *(uint4*)(Bs + r * WSTRIDE + c * 8) = v;
    }
    __syncthreads();

    int w = tid >> 5, lane = tid & 31;
    int wm = (w & 3) * 32;
    int wn = (w >> 2) * 64;

    float acc[2][8][4];
#pragma unroll
    for (int i = 0; i < 2; i++)
#pragma unroll
        for (int j = 0; j < 8; j++)
#pragma unroll
            for (int q = 0; q < 4; q++) acc[i][j][q] = 0.f;

    uint32_t a_addr[2];
#pragma unroll
    for (int i = 0; i < 2; i++)
        a_addr[i] = sbase + AS_OFF +
                    (uint32_t)((wm + i * 16 + (lane & 15)) * WSTRIDE +
                               (lane >> 4) * 8) * 2;
    uint32_t b_addr[4];
#pragma unroll
    for (int jj = 0; jj < 4; jj++)
        b_addr[jj] = sbase + BS_OFF +
                     (uint32_t)((wn + jj * 16 + ((lane >> 4) & 1) * 8 + (lane & 7)) *
                                    WSTRIDE +
                                ((lane >> 3) & 1) * 8) * 2;

#pragma unroll
    for (int s = 0; s < 8; s++) {
        uint32_t a[2][4], b[4][4];
#pragma unroll
        for (int i = 0; i < 2; i++) ldsm4(a[i], a_addr[i] + s * 32);
#pragma unroll
        for (int jj = 0; jj < 4; jj++) ldsm4(b[jj], b_addr[jj] + s * 32);
#pragma unroll
        for (int i = 0; i < 2; i++)
#pragma unroll
            for (int jj = 0; jj < 4; jj++) {
                mma16816(acc[i][2 * jj], a[i], &b[jj][0]);
                mma16816(acc[i][2 * jj + 1], a[i], &b[jj][2]);
            }
    }
    __syncthreads();   // reuse smem as fp32 staging

    float* Cs = (float*)smem;
    int g = lane >> 2, tg = lane & 3;
#pragma unroll
    for (int i = 0; i < 2; i++) {
#pragma unroll
        for (int j = 0; j < 8; j++) {
            int col = wn + j * 8 + tg * 2;
            int r0 = wm + i * 16 + g;
            *(float2*)&Cs[r0 * CFSTR + col] = make_float2(acc[i][j][0], acc[i][j][1]);
            *(float2*)&Cs[(r0 + 8) * CFSTR + col] = make_float2(acc[i][j][2], acc[i][j][3]);
        }
    }
    __syncthreads();

#pragma unroll
    for (int it = 0; it < 16; it++) {
        int idx = it * 256 + tid;
        int r = idx >> 5, c = idx & 31;
        if (nb + r < N) {
            float4 v = *(const float4*)&Cs[r * CFSTR + c * 4];
            *(float4*)&g_gates[(size_t)(nb + r) * 256 + colbase + c * 4] = v;
        }
    }
}

// elementwise GRU update from gates; also clears g_agg for the next iteration.
__global__ void gru_elem_kernel(const float* __restrict__ b_ih,
                                const float* __restrict__ b_hh, int N) {
    int i = blockIdx.x * 256 + threadIdx.x;
    if (i >= N * DIM) return;
    int n = i >> 6, f = i & 63;
    const float* gt = g_gates + (size_t)n * 256;
    float r = 1.f / (1.f + __expf(-(gt[f] + b_ih[f] + b_hh[f])));
    float z = 1.f / (1.f + __expf(-(gt[64 + f] + b_ih[64 + f] + b_hh[64 + f])));
    float inn = gt[128 + f] + b_ih[128 + f];
    float hn  = gt[192 + f] + b_hh[128 + f];
    float ng = tanhf(inn + r * hn);
    g_h[i] = (1.f - z) * ng + z * g_h[i];
    g_agg[i] = 0.f;
}

// msg[e] = h[src[e]] @ Wedge8[e]; HFMA2 accumulation, scatter via atomics.
__global__ void __launch_bounds__(256) msg_scatter_kernel(
    const int* __restrict__ src, const int* __restrict__ dst, int E) {
    __shared__ uint32_t souts[64][68];
    __shared__ int sdst[64];
    int ty = threadIdx.x >> 2;
    int tx = threadIdx.x & 3;
    int e = blockIdx.x * 64 + ty;
    if (e < E) {
        int s = src[e];
#pragma unroll
        for (int q = 0; q < 4; q++) {
            float4 v = *(const float4*)&g_h[(size_t)s * 64 + tx * 16 + q * 4];
            __half hx = __float2half(v.x), hy = __float2half(v.y);
            __half hz = __float2half(v.z), hw = __float2half(v.w);
            __half2 d0 = __halves2half2(hx, hx);
            __half2 d1 = __halves2half2(hy, hy);
            __half2 d2 = __halves2half2(hz, hz);
            __half2 d3 = __halves2half2(hw, hw);
            souts[ty][tx * 16 + q * 4 + 0] = *(uint32_t*)&d0;
            souts[ty][tx * 16 + q * 4 + 1] = *(uint32_t*)&d1;
            souts[ty][tx * 16 + q * 4 + 2] = *(uint32_t*)&d2;
            souts[ty][tx * 16 + q * 4 + 3] = *(uint32_t*)&d3;
        }
        if (tx == 0) sdst[ty] = dst[e];
    }
    __syncthreads();
    if (e >= E) return;
    __half2 hacc[8];
#pragma unroll
    for (int j = 0; j < 8; j++) hacc[j] = __halves2half2(__ushort_as_half(0),
                                                         __ushort_as_half(0));
    const uint8_t* Wrow = g_Wedge8 + (size_t)e * 4096 + tx * 16;
#pragma unroll 8
    for (int d = 0; d < 64; d++) {
        uint32_t a2 = souts[ty][d];
        __half2 ah = *(__half2*)&a2;
        uint4 raw = *(const uint4*)(Wrow + d * 64);
        uint32_t ws[4] = {raw.x, raw.y, raw.z, raw.w};
#pragma unroll
        for (int q = 0; q < 4; q++) {
            uint32_t lo = e4m3x2_to_f16x2((uint16_t)ws[q]);
            uint32_t hi = e4m3x2_to_f16x2((uint16_t)(ws[q] >> 16));
            hacc[2 * q]     = __hfma2(ah, *(__half2*)&lo, hacc[2 * q]);
            hacc[2 * q + 1] = __hfma2(ah, *(__half2*)&hi, hacc[2 * q + 1]);
        }
    }
    int dn = sdst[ty];
    float* ap = g_agg + (size_t)dn * 64 + tx * 16;
#pragma unroll
    for (int j = 0; j < 8; j++) {
        float2 f = __half22float2(hacc[j]);
        atomicAdd(ap + 2 * j, f.x * WSCALE_INV);
        atomicAdd(ap + 2 * j + 1, f.y * WSCALE_INV);
    }
}

// final MLP: warp-per-edge with software-pipelined gathers.
#define FIN_EDGES 64
__global__ void __launch_bounds__(128) final_mlp_kernel(
    const float* __restrict__ ea3, const int* __restrict__ idx_a,
    const int* __restrict__ idx_b, const float* __restrict__ W_l1,
    const float* __restrict__ b_l1, const float* __restrict__ W_l2,
    const float* __restrict__ b_l2, float* __restrict__ out, int E3) {
    __shared__ float wl1[72 * 128];
    __shared__ float swl2[128];
    __shared__ float sbl1[128];
    __shared__ float feat[4][72];
    int tid = threadIdx.x;
    for (int i = tid; i < 72 * 128; i += 128) wl1[i] = W_l1[i];
    swl2[tid] = W_l2[tid];
    sbl1[tid] = b_l1[tid];
    __syncthreads();
    int w = tid >> 5, lane = tid & 31;
    float bl2v = b_l2[0];
    int base = blockIdx.x * FIN_EDGES;

    float p0 = 0.f, p1 = 0.f, p2 = 0.f, p3 = 0.f, pq = 0.f;
    {
        int e = base + w;
        if (e < E3) {
            int a = idx_a[e], b = idx_b[e];
            p0 = g_h[(size_t)a * 64 + lane];
            p1 = g_h[(size_t)b * 64 + lane];
            p2 = g_h[(size_t)a * 64 + 32 + lane];
            p3 = g_h[(size_t)b * 64 + 32 + lane];
            if (lane < 8) pq = ea3[(size_t)e * 8 + lane];
        }
    }
    for (int t = w; t < FIN_EDGES; t += 4) {
        int e = base + t;
        if (e >= E3) break;
        float n0 = 0.f, n1 = 0.f, n2 = 0.f, n3 = 0.f, nq = 0.f;
        int en = base + t + 4;
        if (t + 4 < FIN_EDGES && en < E3) {
            int a = idx_a[en], b = idx_b[en];
            n0 = g_h[(size_t)a * 64 + lane];
            n1 = g_h[(size_t)b * 64 + lane];
            n2 = g_h[(size_t)a * 64 + 32 + lane];
            n3 = g_h[(size_t)b * 64 + 32 + lane];
            if (lane < 8) nq = ea3[(size_t)en * 8 + lane];
        }
        feat[w][lane] = 0.5f * (p0 + p1);
        feat[w][32 + lane] = 0.5f * (p2 + p3);
        if (lane < 8) feat[w][64 + lane] = pq;
        __syncwarp();
        float a0 = sbl1[lane], a1 = sbl1[lane + 32],
              a2 = sbl1[lane + 64], a3 = sbl1[lane + 96];
#pragma unroll 8
        for (int i = 0; i < 72; i++) {
            float f = feat[w][i];
            a0 += f * wl1[i * 128 + lane];
            a1 += f * wl1[i * 128 + lane + 32];
            a2 += f * wl1[i * 128 + lane + 64];
            a3 += f * wl1[i * 128 + lane + 96];
        }
        float s = fmaxf(a0, 0.f) * swl2[lane] + fmaxf(a1, 0.f) * swl2[lane + 32] +
                  fmaxf(a2, 0.f) * swl2[lane + 64] + fmaxf(a3, 0.f) * swl2[lane + 96];
#pragma unroll
        for (int o = 16; o > 0; o >>= 1) s += __shfl_down_sync(0xffffffffu, s, o);
        if (lane == 0) out[e] = s + bl2v;
        __syncwarp();
        p0 = n0; p1 = n1; p2 = n2; p3 = n3; pq = nq;
    }
}

// ---------------- launch ------------------------------------------------------
extern "C" void kernel_launch(void* const* d_in, const int* in_sizes, int n_in,
                              void* d_out, int out_size) {
    const float* x          = (const float*)d_in[0];
    const float* edge_attr  = (const float*)d_in[1];
    const float* edge_attr3 = (const float*)d_in[2];
    const int*   edge_index  = (const int*)d_in[3];
    const int*   edge_index3 = (const int*)d_in[4];
    const float* W_node = (const float*)d_in[5];
    const float* b_node = (const float*)d_in[6];
    const float* W_ea   = (const float*)d_in[7];
    const float* b_ea   = (const float*)d_in[8];
    const float* W_e1   = (const float*)d_in[9];
    const float* b_e1   = (const float*)d_in[10];
    const float* W_e2   = (const float*)d_in[11];
    const float* b_e2   = (const float*)d_in[12];
    const float* conv_bias = (const float*)d_in[13];
    const float* W_ih = (const float*)d_in[14];
    const float* b_ih = (const float*)d_in[15];
    const float* W_hh = (const float*)d_in[16];
    const float* b_hh = (const float*)d_in[17];
    const float* W_l1 = (const float*)d_in[18];
    const float* b_l1 = (const float*)d_in[19];
    const float* W_l2 = (const float*)d_in[20];
    const float* b_l2 = (const float*)d_in[21];

    int N  = in_sizes[0] / 8;
    int E  = in_sizes[1] / 19;
    int E3 = in_sizes[2] / 8;
    const int* src  = edge_index;
    const int* dst  = edge_index + E;
    const int* e3a  = edge_index3;
    const int* e3b  = edge_index3 + E3;
    float* out = (float*)d_out;

    cudaFuncSetAttribute(wedge_mma_kernel,
                         cudaFuncAttributeMaxDynamicSharedMemorySize, WM_SMEM_SIZE);
    cudaFuncSetAttribute(gru_mma_kernel,
                         cudaFuncAttributeMaxDynamicSharedMemorySize, GM_SMEM_SIZE);

    // (1) node MLP + zero agg/cnt
    prep_kernel<<<(N * DIM + 255) / 256, 256>>>(x, W_node, b_node, N);
    // (2) edge MLP (8 edges/block, fp8 out) + degree count + W_e2 transpose (fp8)
    {
        int EB = (E + EDGES_PER_BLK - 1) / EDGES_PER_BLK;
        edge_w2t_kernel<<<EB + 4096, 128>>>(edge_attr, W_ea, b_ea, W_e1, b_e1,
                                            W_e2, dst, E);
    }
    // (3) GRU gate-weight concat (tiny)
    wcat_kernel<<<128, 256>>>(W_ih, W_hh);
    // (4) big GEMM on fp8 tensor cores -> Wedge (e4m3*32)
    {
        dim3 grid((E + 127) / 128, 32);
        wedge_mma_kernel<<<grid, 256, WM_SMEM_SIZE>>>(b_e2, E);
    }
    // (5) invcnt (cnt complete after edge_w2t)
    invcnt_kernel<<<(N + 255) / 256, 256>>>(N);
    // 3 conv + GRU iterations
    dim3 ggrid((N + 127) / 128, 2);
    for (int it = 0; it < 3; it++) {
        msg_scatter_kernel<<<(E + 63) / 64, 256>>>(src, dst, E);
        gru_mma_kernel<<<ggrid, 256, GM_SMEM_SIZE>>>(conv_bias, N);
        gru_elem_kernel<<<(N * DIM + 255) / 256, 256>>>(b_ih, b_hh, N);
    }
    // final pair MLP
    final_mlp_kernel<<<(E3 + FIN_EDGES - 1) / FIN_EDGES, 128>>>(
        edge_attr3, e3a, e3b, W_l1, b_l1, W_l2, b_l2, out, E3);
}

// round 16
// speedup vs baseline: 1.1217x; 1.1217x over previous
#include <cuda_runtime.h>
#include <cuda_fp16.h>
#include <cstdint>
#include <cstddef>

#define NN   25000
#define EE   50000
#define EE3  40000
#define DIM  64

// Wedge stored as e4m3 scaled by 32 (decoded value = stored/32)
#define WSCALE     32.0f
#define WSCALE_INV 0.03125f

// ---------------- scratch (device globals; no allocation at launch time) ----
__device__ float   g_h[NN * DIM];                      // node features / GRU state
__device__ float   g_agg[NN * DIM];                    // scatter-sum accumulator
__device__ __half  g_hr_h[EE * 128];                   // edge hidden (fp16)
__device__ __half  g_W2T[4096 * 128];                  // W_e2 transposed fp16 [col][k]
__device__ uint8_t g_Wedge8[(size_t)EE * DIM * DIM];   // 205 MB per-edge weights (e4m3*32)
__device__ float   g_cnt[NN];
__device__ __half  g_WcatT[256 * 128];                 // GRU gate weights [gate][k]
__device__ float   g_gates[(size_t)NN * 256];          // GEMM gate outputs

// ---------------- helpers -----------------------------------------------------
__device__ __forceinline__ uint32_t smem_to_u32(const void* p) {
    uint32_t a;
    asm("{ .reg .u64 t; cvta.to.shared.u64 t, %1; cvt.u32.u64 %0, t; }"
        : "=r"(a) : "l"(p));
    return a;
}
__device__ __forceinline__ void ldsm4(uint32_t* r, uint32_t addr) {
    asm volatile("ldmatrix.sync.aligned.m8n8.x4.shared.b16 {%0,%1,%2,%3}, [%4];"
                 : "=r"(r[0]), "=r"(r[1]), "=r"(r[2]), "=r"(r[3]) : "r"(addr));
}
// fp32-accumulate HMMA (fastest MMA on this target: fp16-acc AND fp8 both
// measured slower — fp8 mma.sync costs regs 94->137, occ 24%->12%)
__device__ __forceinline__ void mma16816(float* d, const uint32_t* a,
                                         const uint32_t* b) {
    asm volatile(
        "mma.sync.aligned.m16n8k16.row.col.f32.f16.f16.f32 "
        "{%0,%1,%2,%3}, {%4,%5,%6,%7}, {%8,%9}, {%0,%1,%2,%3};"
        : "+f"(d[0]), "+f"(d[1]), "+f"(d[2]), "+f"(d[3])
        : "r"(a[0]), "r"(a[1]), "r"(a[2]), "r"(a[3]), "r"(b[0]), "r"(b[1]));
}
__device__ __forceinline__ uint16_t f32x2_to_e4m3(float lo, float hi) {
    uint16_t r;
    asm("cvt.rn.satfinite.e4m3x2.f32 %0, %1, %2;" : "=h"(r) : "f"(hi), "f"(lo));
    return r;
}
__device__ __forceinline__ uint32_t e4m3x2_to_f16x2(uint16_t v) {
    uint32_t r;
    asm("cvt.rn.f16x2.e4m3x2 %0, %1;" : "=r"(r) : "h"(v));
    return r;
}

// ------- fused prep: node MLP + zero agg/cnt + GRU gate-weight concat ---------
// blocks [0, NB): node work. blocks [NB, NB+128): build WcatT.
__global__ void prep_kernel(const float* __restrict__ x,
                            const float* __restrict__ Wn,
                            const float* __restrict__ bn,
                            const float* __restrict__ W_ih,
                            const float* __restrict__ W_hh, int N, int NB) {
    if ((int)blockIdx.x >= NB) {
        // WcatT[256][128]: rows 0-63 [Wih_r|Whh_r], 64-127 [Wih_z|Whh_z],
        // 128-191 [Wih_n|0], 192-255 [0|Whh_n]
        int i = ((int)blockIdx.x - NB) * 256 + threadIdx.x;
        int g = i >> 7, k = i & 127;
        float v;
        if (g < 128)      v = (k < 64) ? W_ih[g * 64 + k] : W_hh[g * 64 + (k - 64)];
        else if (g < 192) v = (k < 64) ? W_ih[g * 64 + k] : 0.f;
        else              v = (k >= 64) ? W_hh[(g - 64) * 64 + (k - 64)] : 0.f;
        g_WcatT[g * 128 + k] = __float2half(v);
        return;
    }
    int i = blockIdx.x * 256 + threadIdx.x;
    if (i < N) g_cnt[i] = 0.f;
    if (i >= N * DIM) return;
    g_agg[i] = 0.f;
    int n = i >> 6, f = i & 63;
    float acc = bn[f];
#pragma unroll
    for (int k = 0; k < 8; k++) acc += x[n * 8 + k] * Wn[k * DIM + f];
    g_h[i] = fmaxf(acc, 0.f);
}

// -------- fused edge MLP (8 edges/block) + degree count + W_e2 transpose ------
#define EDGES_PER_BLK 8
__global__ void __launch_bounds__(128) edge_w2t_kernel(
    const float* __restrict__ ea_in, const float* __restrict__ W_ea,
    const float* __restrict__ b_ea, const float* __restrict__ W_e1,
    const float* __restrict__ b_e1, const float* __restrict__ W2,
    const int* __restrict__ dst, int E) {
    int tid = threadIdx.x;
    int EB = (E + EDGES_PER_BLK - 1) / EDGES_PER_BLK;
    if ((int)blockIdx.x >= EB) {
        int i = ((int)blockIdx.x - EB) * 128 + tid;
        int n = i & 4095, k = i >> 12;
        g_W2T[(size_t)n * 128 + k] = __float2half(W2[(size_t)k * 4096 + n]);
        return;
    }
    __shared__ float row[EDGES_PER_BLK][20];   // padded
    __shared__ float eah[EDGES_PER_BLK][12];
    int e0 = blockIdx.x * EDGES_PER_BLK;
    int ecnt = min(EDGES_PER_BLK, E - e0);
    for (int i = tid; i < ecnt * 19; i += 128)
        row[i / 19][i % 19] = ea_in[(size_t)e0 * 19 + i];
    if (tid < ecnt) atomicAdd(&g_cnt[dst[e0 + tid]], 1.f);
    __syncthreads();
    if (tid < ecnt * 12) {
        int el = tid / 12, j = tid % 12;
        float a = b_ea[j];
#pragma unroll
        for (int i = 0; i < 19; i++) a += row[el][i] * W_ea[i * 12 + j];
        eah[el][j] = fmaxf(a, 0.f);
    }
    __syncthreads();
    float w[12];
#pragma unroll
    for (int k = 0; k < 12; k++) w[k] = W_e1[k * 128 + tid];
    float be = b_e1[tid];
#pragma unroll
    for (int el = 0; el < EDGES_PER_BLK; el++) {
        if (el >= ecnt) break;
        float a = be;
#pragma unroll
        for (int k = 0; k < 12; k++) a += eah[el][k] * w[k];
        g_hr_h[(size_t)(e0 + el) * 128 + tid] = __float2half(fmaxf(a, 0.f));
    }
}

// ============ HMMA Wedge GEMM (fp32 acc, 8 warps, 32x64 tiles — FROZEN) ======
#define WSTRIDE 136
#define AS_OFF  0
#define BS_OFF  (128 * WSTRIDE * 2)
#define BIAS_OFF (2 * 128 * WSTRIDE * 2)
#define WM_SMEM_SIZE (BIAS_OFF + 128 * 4)
#define CBSTR 144   // byte stride of fp8 staging rows (16-aligned)

__global__ void __launch_bounds__(256) wedge_mma_kernel(
    const float* __restrict__ b2, int E) {
    extern __shared__ char smem[];
    __half* As = (__half*)(smem + AS_OFF);
    __half* Bs = (__half*)(smem + BS_OFF);
    float* sbias = (float*)(smem + BIAS_OFF);
    uint32_t sbase = smem_to_u32(smem);
    int tid = threadIdx.x;
    int ebase = blockIdx.x * 128;
    int colbase = blockIdx.y * 128;

    if (tid < 128) sbias[tid] = b2[colbase + tid];

#pragma unroll
    for (int it = 0; it < 8; it++) {
        int idx = it * 256 + tid;
        int r = idx >> 4, c = idx & 15;
        uint4 v = make_uint4(0, 0, 0, 0);
        if (ebase + r < E)
            v = *(const uint4*)(g_hr_h + ((size_t)(ebase + r) << 7) + c * 8);
        *(uint4*)(As + r * WSTRIDE + c * 8) = v;
    }
#pragma unroll
    for (int it = 0; it < 8; it++) {
        int idx = it * 256 + tid;
        int r = idx >> 4, c = idx & 15;
        uint4 v = *(const uint4*)(g_W2T + ((size_t)(colbase + r) << 7) + c * 8);
        *(uint4*)(Bs + r * WSTRIDE + c * 8) = v;
    }
    __syncthreads();

    int w = tid >> 5, lane = tid & 31;
    int wm = (w & 3) * 32;
    int wn = (w >> 2) * 64;

    float acc[2][8][4];
#pragma unroll
    for (int i = 0; i < 2; i++)
#pragma unroll
        for (int j = 0; j < 8; j++)
#pragma unroll
            for (int q = 0; q < 4; q++) acc[i][j][q] = 0.f;

    uint32_t a_addr[2];
#pragma unroll
    for (int i = 0; i < 2; i++)
        a_addr[i] = sbase + AS_OFF +
                    (uint32_t)((wm + i * 16 + (lane & 15)) * WSTRIDE +
                               (lane >> 4) * 8) * 2;
    uint32_t b_addr[4];
#pragma unroll
    for (int jj = 0; jj < 4; jj++)
        b_addr[jj] = sbase + BS_OFF +
                     (uint32_t)((wn + jj * 16 + ((lane >> 4) & 1) * 8 + (lane & 7)) *
                                    WSTRIDE +
                                ((lane >> 3) & 1) * 8) * 2;

#pragma unroll
    for (int s = 0; s < 8; s++) {
        uint32_t a[2][4], b[4][4];
#pragma unroll
        for (int i = 0; i < 2; i++) ldsm4(a[i], a_addr[i] + s * 32);
#pragma unroll
        for (int jj = 0; jj < 4; jj++) ldsm4(b[jj], b_addr[jj] + s * 32);
#pragma unroll
        for (int i = 0; i < 2; i++)
#pragma unroll
            for (int jj = 0; jj < 4; jj++) {
                mma16816(acc[i][2 * jj], a[i], &b[jj][0]);
                mma16816(acc[i][2 * jj + 1], a[i], &b[jj][2]);
            }
    }
    __syncthreads();   // reuse smem as fp8 staging

    uint8_t* Cs = (uint8_t*)smem;
    int g = lane >> 2, tg = lane & 3;
#pragma unroll
    for (int i = 0; i < 2; i++) {
#pragma unroll
        for (int j = 0; j < 8; j++) {
            int col = wn + j * 8 + tg * 2;
            float b0 = sbias[col], b1 = sbias[col + 1];
            int r0 = wm + i * 16 + g;
            uint16_t p0 = f32x2_to_e4m3((acc[i][j][0] + b0) * WSCALE,
                                        (acc[i][j][1] + b1) * WSCALE);
            uint16_t p1 = f32x2_to_e4m3((acc[i][j][2] + b0) * WSCALE,
                                        (acc[i][j][3] + b1) * WSCALE);
            *(uint16_t*)(Cs + r0 * CBSTR + col) = p0;
            *(uint16_t*)(Cs + (r0 + 8) * CBSTR + col) = p1;
        }
    }
    __syncthreads();

#pragma unroll
    for (int it = 0; it < 4; it++) {
        int idx = it * 256 + tid;
        int r = idx >> 3, c = idx & 7;
        if (ebase + r < E) {
            uint4 v = *(const uint4*)(Cs + r * CBSTR + c * 16);
            *(uint4*)(g_Wedge8 + (size_t)(ebase + r) * 4096 + colbase + c * 16) = v;
        }
    }
}

// ============ HMMA GRU gate GEMM (m + invcnt computed in A-load) ==============
#define GM_SMEM_SIZE (2 * 128 * WSTRIDE * 2)
#define CFSTR 132   // float stride of fp32 staging rows

__global__ void __launch_bounds__(256) gru_mma_kernel(
    const float* __restrict__ conv_bias, int N) {
    extern __shared__ char smem[];
    __half* As = (__half*)(smem + AS_OFF);
    __half* Bs = (__half*)(smem + BS_OFF);
    uint32_t sbase = smem_to_u32(smem);
    int tid = threadIdx.x;
    int nb = blockIdx.x * 128;
    int colbase = blockIdx.y * 128;

    // A: build fp16 [m|h] tile from fp32 agg/h (chunks c<8 -> m, c>=8 -> h)
#pragma unroll
    for (int it = 0; it < 8; it++) {
        int idx = it * 256 + tid;
        int r = idx >> 4, c = idx & 15;
        int n = nb + r;
        uint4 o = make_uint4(0, 0, 0, 0);
        if (n < N) {
            int f0 = (c & 7) * 8;
            float4 v0, v1;
            if (c < 8) {
                v0 = *(const float4*)(g_agg + (size_t)n * 64 + f0);
                v1 = *(const float4*)(g_agg + (size_t)n * 64 + f0 + 4);
                float ic = 1.f / fmaxf(g_cnt[n], 1.f);   // invcnt folded in
                float4 cb0 = *(const float4*)(conv_bias + f0);
                float4 cb1 = *(const float4*)(conv_bias + f0 + 4);
                v0.x = fmaxf(v0.x * ic + cb0.x, 0.f);
                v0.y = fmaxf(v0.y * ic + cb0.y, 0.f);
                v0.z = fmaxf(v0.z * ic + cb0.z, 0.f);
                v0.w = fmaxf(v0.w * ic + cb0.w, 0.f);
                v1.x = fmaxf(v1.x * ic + cb1.x, 0.f);
                v1.y = fmaxf(v1.y * ic + cb1.y, 0.f);
                v1.z = fmaxf(v1.z * ic + cb1.z, 0.f);
                v1.w = fmaxf(v1.w * ic + cb1.w, 0.f);
            } else {
                v0 = *(const float4*)(g_h + (size_t)n * 64 + f0);
                v1 = *(const float4*)(g_h + (size_t)n * 64 + f0 + 4);
            }
            __half2 h0 = __floats2half2_rn(v0.x, v0.y);
            __half2 h1 = __floats2half2_rn(v0.z, v0.w);
            __half2 h2 = __floats2half2_rn(v1.x, v1.y);
            __half2 h3 = __floats2half2_rn(v1.z, v1.w);
            o.x = *(uint32_t*)&h0; o.y = *(uint32_t*)&h1;
            o.z = *(uint32_t*)&h2; o.w = *(uint32_t*)&h3;
        }
        *(uint4*)(As + r * WSTRIDE + c * 8) = o;
    }
#pragma unroll
    for (int it = 0; it < 8; it++) {
        int idx = it * 256 + tid;
        int r = idx >> 4, c = idx & 15;
        uint4 v = *(const uint4*)(g_WcatT + ((size_t)(colbase + r) << 7) + c * 8);
        *(uint4*)(Bs + r * WSTRIDE + c * 8) = v;
    }
    __syncthreads();

    int w = tid >> 5, lane = tid & 31;
    int wm = (w & 3) * 32;
    int wn = (w >> 2) * 64;

    float acc[2][8][4];
#pragma unroll
    for (int i = 0; i < 2; i++)
#pragma unroll
        for (int j = 0; j < 8; j++)
#pragma unroll
            for (int q = 0; q < 4; q++) acc[i][j][q] = 0.f;

    uint32_t a_addr[2];
#pragma unroll
    for (int i = 0; i < 2; i++)
        a_addr[i] = sbase + AS_OFF +
                    (uint32_t)((wm + i * 16 + (lane & 15)) * WSTRIDE +
                               (lane >> 4) * 8) * 2;
    uint32_t b_addr[4];
#pragma unroll
    for (int jj = 0; jj < 4; jj++)
        b_addr[jj] = sbase + BS_OFF +
                     (uint32_t)((wn + jj * 16 + ((lane >> 4) & 1) * 8 + (lane & 7)) *
                                    WSTRIDE +
                                ((lane >> 3) & 1) * 8) * 2;

#pragma unroll
    for (int s = 0; s < 8; s++) {
        uint32_t a[2][4], b[4][4];
#pragma unroll
        for (int i = 0; i < 2; i++) ldsm4(a[i], a_addr[i] + s * 32);
#pragma unroll
        for (int jj = 0; jj < 4; jj++) ldsm4(b[jj], b_addr[jj] + s * 32);
#pragma unroll
        for (int i = 0; i < 2; i++)
#pragma unroll
            for (int jj = 0; jj < 4; jj++) {
                mma16816(acc[i][2 * jj], a[i], &b[jj][0]);
                mma16816(acc[i][2 * jj + 1], a[i], &b[jj][2]);
            }
    }
    __syncthreads();   // reuse smem as fp32 staging

    float* Cs = (float*)smem;
    int g = lane >> 2, tg = lane & 3;
#pragma unroll
    for (int i = 0; i < 2; i++) {
#pragma unroll
        for (int j = 0; j < 8; j++) {
            int col = wn + j * 8 + tg * 2;
            int r0 = wm + i * 16 + g;
            *(float2*)&Cs[r0 * CFSTR + col] = make_float2(acc[i][j][0], acc[i][j][1]);
            *(float2*)&Cs[(r0 + 8) * CFSTR + col] = make_float2(acc[i][j][2], acc[i][j][3]);
        }
    }
    __syncthreads();

#pragma unroll
    for (int it = 0; it < 16; it++) {
        int idx = it * 256 + tid;
        int r = idx >> 5, c = idx & 31;
        if (nb + r < N) {
            float4 v = *(const float4*)&Cs[r * CFSTR + c * 4];
            *(float4*)&g_gates[(size_t)(nb + r) * 256 + colbase + c * 4] = v;
        }
    }
}

// elementwise GRU update from gates; also clears g_agg for the next iteration.
__global__ void gru_elem_kernel(const float* __restrict__ b_ih,
                                const float* __restrict__ b_hh, int N) {
    int i = blockIdx.x * 256 + threadIdx.x;
    if (i >= N * DIM) return;
    int n = i >> 6, f = i & 63;
    const float* gt = g_gates + (size_t)n * 256;
    float r = 1.f / (1.f + __expf(-(gt[f] + b_ih[f] + b_hh[f])));
    float z = 1.f / (1.f + __expf(-(gt[64 + f] + b_ih[64 + f] + b_hh[64 + f])));
    float inn = gt[128 + f] + b_ih[128 + f];
    float hn  = gt[192 + f] + b_hh[128 + f];
    float ng = tanhf(inn + r * hn);
    g_h[i] = (1.f - z) * ng + z * g_h[i];
    g_agg[i] = 0.f;
}

// msg[e] = h[src[e]] @ Wedge8[e]; HFMA2 accumulation, scatter via atomics.
__global__ void __launch_bounds__(256) msg_scatter_kernel(
    const int* __restrict__ src, const int* __restrict__ dst, int E) {
    __shared__ uint32_t souts[64][68];
    __shared__ int sdst[64];
    int ty = threadIdx.x >> 2;
    int tx = threadIdx.x & 3;
    int e = blockIdx.x * 64 + ty;
    if (e < E) {
        int s = src[e];
#pragma unroll
        for (int q = 0; q < 4; q++) {
            float4 v = *(const float4*)&g_h[(size_t)s * 64 + tx * 16 + q * 4];
            __half hx = __float2half(v.x), hy = __float2half(v.y);
            __half hz = __float2half(v.z), hw = __float2half(v.w);
            __half2 d0 = __halves2half2(hx, hx);
            __half2 d1 = __halves2half2(hy, hy);
            __half2 d2 = __halves2half2(hz, hz);
            __half2 d3 = __halves2half2(hw, hw);
            souts[ty][tx * 16 + q * 4 + 0] = *(uint32_t*)&d0;
            souts[ty][tx * 16 + q * 4 + 1] = *(uint32_t*)&d1;
            souts[ty][tx * 16 + q * 4 + 2] = *(uint32_t*)&d2;
            souts[ty][tx * 16 + q * 4 + 3] = *(uint32_t*)&d3;
        }
        if (tx == 0) sdst[ty] = dst[e];
    }
    __syncthreads();
    if (e >= E) return;
    __half2 hacc[8];
#pragma unroll
    for (int j = 0; j < 8; j++) hacc[j] = __halves2half2(__ushort_as_half(0),
                                                         __ushort_as_half(0));
    const uint8_t* Wrow = g_Wedge8 + (size_t)e * 4096 + tx * 16;
#pragma unroll 8
    for (int d = 0; d < 64; d++) {
        uint32_t a2 = souts[ty][d];
        __half2 ah = *(__half2*)&a2;
        uint4 raw = *(const uint4*)(Wrow + d * 64);
        uint32_t ws[4] = {raw.x, raw.y, raw.z, raw.w};
#pragma unroll
        for (int q = 0; q < 4; q++) {
            uint32_t lo = e4m3x2_to_f16x2((uint16_t)ws[q]);
            uint32_t hi = e4m3x2_to_f16x2((uint16_t)(ws[q] >> 16));
            hacc[2 * q]     = __hfma2(ah, *(__half2*)&lo, hacc[2 * q]);
            hacc[2 * q + 1] = __hfma2(ah, *(__half2*)&hi, hacc[2 * q + 1]);
        }
    }
    int dn = sdst[ty];
    float* ap = g_agg + (size_t)dn * 64 + tx * 16;
#pragma unroll
    for (int j = 0; j < 8; j++) {
        float2 f = __half22float2(hacc[j]);
        atomicAdd(ap + 2 * j, f.x * WSCALE_INV);
        atomicAdd(ap + 2 * j + 1, f.y * WSCALE_INV);
    }
}

// final MLP: warp-per-edge with software-pipelined gathers.
#define FIN_EDGES 64
__global__ void __launch_bounds__(128) final_mlp_kernel(
    const float* __restrict__ ea3, const int* __restrict__ idx_a,
    const int* __restrict__ idx_b, const float* __restrict__ W_l1,
    const float* __restrict__ b_l1, const float* __restrict__ W_l2,
    const float* __restrict__ b_l2, float* __restrict__ out, int E3) {
    __shared__ float wl1[72 * 128];
    __shared__ float swl2[128];
    __shared__ float sbl1[128];
    __shared__ float feat[4][72];
    int tid = threadIdx.x;
    for (int i = tid; i < 72 * 128; i += 128) wl1[i] = W_l1[i];
    swl2[tid] = W_l2[tid];
    sbl1[tid] = b_l1[tid];
    __syncthreads();
    int w = tid >> 5, lane = tid & 31;
    float bl2v = b_l2[0];
    int base = blockIdx.x * FIN_EDGES;

    float p0 = 0.f, p1 = 0.f, p2 = 0.f, p3 = 0.f, pq = 0.f;
    {
        int e = base + w;
        if (e < E3) {
            int a = idx_a[e], b = idx_b[e];
            p0 = g_h[(size_t)a * 64 + lane];
            p1 = g_h[(size_t)b * 64 + lane];
            p2 = g_h[(size_t)a * 64 + 32 + lane];
            p3 = g_h[(size_t)b * 64 + 32 + lane];
            if (lane < 8) pq = ea3[(size_t)e * 8 + lane];
        }
    }
    for (int t = w; t < FIN_EDGES; t += 4) {
        int e = base + t;
        if (e >= E3) break;
        float n0 = 0.f, n1 = 0.f, n2 = 0.f, n3 = 0.f, nq = 0.f;
        int en = base + t + 4;
        if (t + 4 < FIN_EDGES && en < E3) {
            int a = idx_a[en], b = idx_b[en];
            n0 = g_h[(size_t)a * 64 + lane];
            n1 = g_h[(size_t)b * 64 + lane];
            n2 = g_h[(size_t)a * 64 + 32 + lane];
            n3 = g_h[(size_t)b * 64 + 32 + lane];
            if (lane < 8) nq = ea3[(size_t)en * 8 + lane];
        }
        feat[w][lane] = 0.5f * (p0 + p1);
        feat[w][32 + lane] = 0.5f * (p2 + p3);
        if (lane < 8) feat[w][64 + lane] = pq;
        __syncwarp();
        float a0 = sbl1[lane], a1 = sbl1[lane + 32],
              a2 = sbl1[lane + 64], a3 = sbl1[lane + 96];
#pragma unroll 8
        for (int i = 0; i < 72; i++) {
            float f = feat[w][i];
            a0 += f * wl1[i * 128 + lane];
            a1 += f * wl1[i * 128 + lane + 32];
            a2 += f * wl1[i * 128 + lane + 64];
            a3 += f * wl1[i * 128 + lane + 96];
        }
        float s = fmaxf(a0, 0.f) * swl2[lane] + fmaxf(a1, 0.f) * swl2[lane + 32] +
                  fmaxf(a2, 0.f) * swl2[lane + 64] + fmaxf(a3, 0.f) * swl2[lane + 96];
#pragma unroll
        for (int o = 16; o > 0; o >>= 1) s += __shfl_down_sync(0xffffffffu, s, o);
        if (lane == 0) out[e] = s + bl2v;
        __syncwarp();
        p0 = n0; p1 = n1; p2 = n2; p3 = n3; pq = nq;
    }
}

// ---------------- launch ------------------------------------------------------
extern "C" void kernel_launch(void* const* d_in, const int* in_sizes, int n_in,
                              void* d_out, int out_size) {
    const float* x          = (const float*)d_in[0];
    const float* edge_attr  = (const float*)d_in[1];
    const float* edge_attr3 = (const float*)d_in[2];
    const int*   edge_index  = (const int*)d_in[3];
    const int*   edge_index3 = (const int*)d_in[4];
    const float* W_node = (const float*)d_in[5];
    const float* b_node = (const float*)d_in[6];
    const float* W_ea   = (const float*)d_in[7];
    const float* b_ea   = (const float*)d_in[8];
    const float* W_e1   = (const float*)d_in[9];
    const float* b_e1   = (const float*)d_in[10];
    const float* W_e2   = (const float*)d_in[11];
    const float* b_e2   = (const float*)d_in[12];
    const float* conv_bias = (const float*)d_in[13];
    const float* W_ih = (const float*)d_in[14];
    const float* b_ih = (const float*)d_in[15];
    const float* W_hh = (const float*)d_in[16];
    const float* b_hh = (const float*)d_in[17];
    const float* W_l1 = (const float*)d_in[18];
    const float* b_l1 = (const float*)d_in[19];
    const float* W_l2 = (const float*)d_in[20];
    const float* b_l2 = (const float*)d_in[21];

    int N  = in_sizes[0] / 8;
    int E  = in_sizes[1] / 19;
    int E3 = in_sizes[2] / 8;
    const int* src  = edge_index;
    const int* dst  = edge_index + E;
    const int* e3a  = edge_index3;
    const int* e3b  = edge_index3 + E3;
    float* out = (float*)d_out;

    cudaFuncSetAttribute(wedge_mma_kernel,
                         cudaFuncAttributeMaxDynamicSharedMemorySize, WM_SMEM_SIZE);
    cudaFuncSetAttribute(gru_mma_kernel,
                         cudaFuncAttributeMaxDynamicSharedMemorySize, GM_SMEM_SIZE);

    // (1) node MLP + zero agg/cnt + WcatT build (fused)
    {
        int NB = (N * DIM + 255) / 256;
        prep_kernel<<<NB + 128, 256>>>(x, W_node, b_node, W_ih, W_hh, N, NB);
    }
    // (2) edge MLP (8 edges/block) + degree count + W_e2 transpose (fused)
    {
        int EB = (E + EDGES_PER_BLK - 1) / EDGES_PER_BLK;
        edge_w2t_kernel<<<EB + 4096, 128>>>(edge_attr, W_ea, b_ea, W_e1, b_e1,
                                            W_e2, dst, E);
    }
    // (3) big GEMM on tensor cores -> Wedge (e4m3*32)
    {
        dim3 grid((E + 127) / 128, 32);
        wedge_mma_kernel<<<grid, 256, WM_SMEM_SIZE>>>(b_e2, E);
    }
    // 3 conv + GRU iterations
    dim3 ggrid((N + 127) / 128, 2);
    for (int it = 0; it < 3; it++) {
        msg_scatter_kernel<<<(E + 63) / 64, 256>>>(src, dst, E);
        gru_mma_kernel<<<ggrid, 256, GM_SMEM_SIZE>>>(conv_bias, N);
        gru_elem_kernel<<<(N * DIM + 255) / 256, 256>>>(b_ih, b_hh, N);
    }
    // final pair MLP
    final_mlp_kernel<<<(E3 + FIN_EDGES - 1) / FIN_EDGES, 128>>>(
        edge_attr3, e3a, e3b, W_l1, b_l1, W_l2, b_l2, out, E3);
}

// round 17
// speedup vs baseline: 1.1596x; 1.0337x over previous
#include <cuda_runtime.h>
#include <cuda_fp16.h>
#include <cstdint>
#include <cstddef>

#define NN   25000
#define EE   50000
#define EE3  40000
#define DIM  64

// Wedge stored as e4m3 scaled by 32 (decoded value = stored/32)
#define WSCALE     32.0f
#define WSCALE_INV 0.03125f

// ---------------- scratch (device globals; no allocation at launch time) ----
__device__ float   g_h[NN * DIM];                      // node features / GRU state
__device__ float   g_agg[NN * DIM];                    // scatter-sum accumulator
__device__ __half  g_hr_h[EE * 128];                   // edge hidden (fp16)
__device__ __half  g_W2T[4096 * 128];                  // W_e2 transposed fp16 [col][k]
__device__ uint8_t g_Wedge8[(size_t)EE * DIM * DIM];   // 205 MB per-edge weights (e4m3*32)
__device__ float   g_cnt[NN];
__device__ __half  g_WcatT[256 * 128];                 // GRU gate weights [gate][k]
__device__ float   g_gates[(size_t)NN * 256];          // GEMM gate outputs

// ---------------- helpers -----------------------------------------------------
__device__ __forceinline__ uint32_t smem_to_u32(const void* p) {
    uint32_t a;
    asm("{ .reg .u64 t; cvta.to.shared.u64 t, %1; cvt.u32.u64 %0, t; }"
        : "=r"(a) : "l"(p));
    return a;
}
__device__ __forceinline__ void ldsm4(uint32_t* r, uint32_t addr) {
    asm volatile("ldmatrix.sync.aligned.m8n8.x4.shared.b16 {%0,%1,%2,%3}, [%4];"
                 : "=r"(r[0]), "=r"(r[1]), "=r"(r[2]), "=r"(r[3]) : "r"(addr));
}
// fp32-accumulate HMMA (fastest MMA on this target: fp16-acc AND fp8 both
// measured slower — fp8 mma.sync costs regs 94->137, occ 24%->12%)
__device__ __forceinline__ void mma16816(float* d, const uint32_t* a,
                                         const uint32_t* b) {
    asm volatile(
        "mma.sync.aligned.m16n8k16.row.col.f32.f16.f16.f32 "
        "{%0,%1,%2,%3}, {%4,%5,%6,%7}, {%8,%9}, {%0,%1,%2,%3};"
        : "+f"(d[0]), "+f"(d[1]), "+f"(d[2]), "+f"(d[3])
        : "r"(a[0]), "r"(a[1]), "r"(a[2]), "r"(a[3]), "r"(b[0]), "r"(b[1]));
}
__device__ __forceinline__ uint16_t f32x2_to_e4m3(float lo, float hi) {
    uint16_t r;
    asm("cvt.rn.satfinite.e4m3x2.f32 %0, %1, %2;" : "=h"(r) : "f"(hi), "f"(lo));
    return r;
}
__device__ __forceinline__ uint32_t e4m3x2_to_f16x2(uint16_t v) {
    uint32_t r;
    asm("cvt.rn.f16x2.e4m3x2 %0, %1;" : "=r"(r) : "h"(v));
    return r;
}

// ------- fused prep: node MLP + zero agg/cnt + GRU gate-weight concat ---------
__global__ void prep_kernel(const float* __restrict__ x,
                            const float* __restrict__ Wn,
                            const float* __restrict__ bn,
                            const float* __restrict__ W_ih,
                            const float* __restrict__ W_hh, int N, int NB) {
    if ((int)blockIdx.x >= NB) {
        int i = ((int)blockIdx.x - NB) * 256 + threadIdx.x;
        int g = i >> 7, k = i & 127;
        float v;
        if (g < 128)      v = (k < 64) ? W_ih[g * 64 + k] : W_hh[g * 64 + (k - 64)];
        else if (g < 192) v = (k < 64) ? W_ih[g * 64 + k] : 0.f;
        else              v = (k >= 64) ? W_hh[(g - 64) * 64 + (k - 64)] : 0.f;
        g_WcatT[g * 128 + k] = __float2half(v);
        return;
    }
    int i = blockIdx.x * 256 + threadIdx.x;
    if (i < N) g_cnt[i] = 0.f;
    if (i >= N * DIM) return;
    g_agg[i] = 0.f;
    int n = i >> 6, f = i & 63;
    float acc = bn[f];
#pragma unroll
    for (int k = 0; k < 8; k++) acc += x[n * 8 + k] * Wn[k * DIM + f];
    g_h[i] = fmaxf(acc, 0.f);
}

// -------- fused edge MLP (8 edges/block) + degree count + W_e2 transpose ------
#define EDGES_PER_BLK 8
__global__ void __launch_bounds__(128) edge_w2t_kernel(
    const float* __restrict__ ea_in, const float* __restrict__ W_ea,
    const float* __restrict__ b_ea, const float* __restrict__ W_e1,
    const float* __restrict__ b_e1, const float* __restrict__ W2,
    const int* __restrict__ dst, int E) {
    int tid = threadIdx.x;
    int EB = (E + EDGES_PER_BLK - 1) / EDGES_PER_BLK;
    if ((int)blockIdx.x >= EB) {
        int i = ((int)blockIdx.x - EB) * 128 + tid;
        int n = i & 4095, k = i >> 12;
        g_W2T[(size_t)n * 128 + k] = __float2half(W2[(size_t)k * 4096 + n]);
        return;
    }
    __shared__ float row[EDGES_PER_BLK][20];   // padded
    __shared__ float eah[EDGES_PER_BLK][12];
    int e0 = blockIdx.x * EDGES_PER_BLK;
    int ecnt = min(EDGES_PER_BLK, E - e0);
    for (int i = tid; i < ecnt * 19; i += 128)
        row[i / 19][i % 19] = ea_in[(size_t)e0 * 19 + i];
    if (tid < ecnt) atomicAdd(&g_cnt[dst[e0 + tid]], 1.f);
    __syncthreads();
    if (tid < ecnt * 12) {
        int el = tid / 12, j = tid % 12;
        float a = b_ea[j];
#pragma unroll
        for (int i = 0; i < 19; i++) a += row[el][i] * W_ea[i * 12 + j];
        eah[el][j] = fmaxf(a, 0.f);
    }
    __syncthreads();
    float w[12];
#pragma unroll
    for (int k = 0; k < 12; k++) w[k] = W_e1[k * 128 + tid];
    float be = b_e1[tid];
#pragma unroll
    for (int el = 0; el < EDGES_PER_BLK; el++) {
        if (el >= ecnt) break;
        float a = be;
#pragma unroll
        for (int k = 0; k < 12; k++) a += eah[el][k] * w[k];
        g_hr_h[(size_t)(e0 + el) * 128 + tid] = __float2half(fmaxf(a, 0.f));
    }
}

// ============ HMMA Wedge GEMM (fp32 acc, 8 warps, 32x64 tiles — FROZEN) ======
#define WSTRIDE 136
#define AS_OFF  0
#define BS_OFF  (128 * WSTRIDE * 2)
#define BIAS_OFF (2 * 128 * WSTRIDE * 2)
#define WM_SMEM_SIZE (BIAS_OFF + 128 * 4)
#define CBSTR 144   // byte stride of fp8 staging rows (16-aligned)

__global__ void __launch_bounds__(256) wedge_mma_kernel(
    const float* __restrict__ b2, int E) {
    extern __shared__ char smem[];
    __half* As = (__half*)(smem + AS_OFF);
    __half* Bs = (__half*)(smem + BS_OFF);
    float* sbias = (float*)(smem + BIAS_OFF);
    uint32_t sbase = smem_to_u32(smem);
    int tid = threadIdx.x;
    int ebase = blockIdx.x * 128;
    int colbase = blockIdx.y * 128;

    if (tid < 128) sbias[tid] = b2[colbase + tid];

#pragma unroll
    for (int it = 0; it < 8; it++) {
        int idx = it * 256 + tid;
        int r = idx >> 4, c = idx & 15;
        uint4 v = make_uint4(0, 0, 0, 0);
        if (ebase + r < E)
            v = *(const uint4*)(g_hr_h + ((size_t)(ebase + r) << 7) + c * 8);
        *(uint4*)(As + r * WSTRIDE + c * 8) = v;
    }
#pragma unroll
    for (int it = 0; it < 8; it++) {
        int idx = it * 256 + tid;
        int r = idx >> 4, c = idx & 15;
        uint4 v = *(const uint4*)(g_W2T + ((size_t)(colbase + r) << 7) + c * 8);
        *(uint4*)(Bs + r * WSTRIDE + c * 8) = v;
    }
    __syncthreads();

    int w = tid >> 5, lane = tid & 31;
    int wm = (w & 3) * 32;
    int wn = (w >> 2) * 64;

    float acc[2][8][4];
#pragma unroll
    for (int i = 0; i < 2; i++)
#pragma unroll
        for (int j = 0; j < 8; j++)
#pragma unroll
            for (int q = 0; q < 4; q++) acc[i][j][q] = 0.f;

    uint32_t a_addr[2];
#pragma unroll
    for (int i = 0; i < 2; i++)
        a_addr[i] = sbase + AS_OFF +
                    (uint32_t)((wm + i * 16 + (lane & 15)) * WSTRIDE +
                               (lane >> 4) * 8) * 2;
    uint32_t b_addr[4];
#pragma unroll
    for (int jj = 0; jj < 4; jj++)
        b_addr[jj] = sbase + BS_OFF +
                     (uint32_t)((wn + jj * 16 + ((lane >> 4) & 1) * 8 + (lane & 7)) *
                                    WSTRIDE +
                                ((lane >> 3) & 1) * 8) * 2;

#pragma unroll
    for (int s = 0; s < 8; s++) {
        uint32_t a[2][4], b[4][4];
#pragma unroll
        for (int i = 0; i < 2; i++) ldsm4(a[i], a_addr[i] + s * 32);
#pragma unroll
        for (int jj = 0; jj < 4; jj++) ldsm4(b[jj], b_addr[jj] + s * 32);
#pragma unroll
        for (int i = 0; i < 2; i++)
#pragma unroll
            for (int jj = 0; jj < 4; jj++) {
                mma16816(acc[i][2 * jj], a[i], &b[jj][0]);
                mma16816(acc[i][2 * jj + 1], a[i], &b[jj][2]);
            }
    }
    __syncthreads();   // reuse smem as fp8 staging

    uint8_t* Cs = (uint8_t*)smem;
    int g = lane >> 2, tg = lane & 3;
#pragma unroll
    for (int i = 0; i < 2; i++) {
#pragma unroll
        for (int j = 0; j < 8; j++) {
            int col = wn + j * 8 + tg * 2;
            float b0 = sbias[col], b1 = sbias[col + 1];
            int r0 = wm + i * 16 + g;
            uint16_t p0 = f32x2_to_e4m3((acc[i][j][0] + b0) * WSCALE,
                                        (acc[i][j][1] + b1) * WSCALE);
            uint16_t p1 = f32x2_to_e4m3((acc[i][j][2] + b0) * WSCALE,
                                        (acc[i][j][3] + b1) * WSCALE);
            *(uint16_t*)(Cs + r0 * CBSTR + col) = p0;
            *(uint16_t*)(Cs + (r0 + 8) * CBSTR + col) = p1;
        }
    }
    __syncthreads();

#pragma unroll
    for (int it = 0; it < 4; it++) {
        int idx = it * 256 + tid;
        int r = idx >> 3, c = idx & 7;
        if (ebase + r < E) {
            uint4 v = *(const uint4*)(Cs + r * CBSTR + c * 16);
            *(uint4*)(g_Wedge8 + (size_t)(ebase + r) * 4096 + colbase + c * 16) = v;
        }
    }
}

// ============ HMMA GRU gate GEMM (m + invcnt computed in A-load) ==============
#define GM_SMEM_SIZE (2 * 128 * WSTRIDE * 2)
#define CFSTR 132   // float stride of fp32 staging rows

__global__ void __launch_bounds__(256) gru_mma_kernel(
    const float* __restrict__ conv_bias, int N) {
    extern __shared__ char smem[];
    __half* As = (__half*)(smem + AS_OFF);
    __half* Bs = (__half*)(smem + BS_OFF);
    uint32_t sbase = smem_to_u32(smem);
    int tid = threadIdx.x;
    int nb = blockIdx.x * 128;
    int colbase = blockIdx.y * 128;

#pragma unroll
    for (int it = 0; it < 8; it++) {
        int idx = it * 256 + tid;
        int r = idx >> 4, c = idx & 15;
        int n = nb + r;
        uint4 o = make_uint4(0, 0, 0, 0);
        if (n < N) {
            int f0 = (c & 7) * 8;
            float4 v0, v1;
            if (c < 8) {
                v0 = *(const float4*)(g_agg + (size_t)n * 64 + f0);
                v1 = *(const float4*)(g_agg + (size_t)n * 64 + f0 + 4);
                float ic = 1.f / fmaxf(g_cnt[n], 1.f);
                float4 cb0 = *(const float4*)(conv_bias + f0);
                float4 cb1 = *(const float4*)(conv_bias + f0 + 4);
                v0.x = fmaxf(v0.x * ic + cb0.x, 0.f);
                v0.y = fmaxf(v0.y * ic + cb0.y, 0.f);
                v0.z = fmaxf(v0.z * ic + cb0.z, 0.f);
                v0.w = fmaxf(v0.w * ic + cb0.w, 0.f);
                v1.x = fmaxf(v1.x * ic + cb1.x, 0.f);
                v1.y = fmaxf(v1.y * ic + cb1.y, 0.f);
                v1.z = fmaxf(v1.z * ic + cb1.z, 0.f);
                v1.w = fmaxf(v1.w * ic + cb1.w, 0.f);
            } else {
                v0 = *(const float4*)(g_h + (size_t)n * 64 + f0);
                v1 = *(const float4*)(g_h + (size_t)n * 64 + f0 + 4);
            }
            __half2 h0 = __floats2half2_rn(v0.x, v0.y);
            __half2 h1 = __floats2half2_rn(v0.z, v0.w);
            __half2 h2 = __floats2half2_rn(v1.x, v1.y);
            __half2 h3 = __floats2half2_rn(v1.z, v1.w);
            o.x = *(uint32_t*)&h0; o.y = *(uint32_t*)&h1;
            o.z = *(uint32_t*)&h2; o.w = *(uint32_t*)&h3;
        }
        *(uint4*)(As + r * WSTRIDE + c * 8) = o;
    }
#pragma unroll
    for (int it = 0; it < 8; it++) {
        int idx = it * 256 + tid;
        int r = idx >> 4, c = idx & 15;
        uint4 v = *(const uint4*)(g_WcatT + ((size_t)(colbase + r) << 7) + c * 8);
        *(uint4*)(Bs + r * WSTRIDE + c * 8) = v;
    }
    __syncthreads();

    int w = tid >> 5, lane = tid & 31;
    int wm = (w & 3) * 32;
    int wn = (w >> 2) * 64;

    float acc[2][8][4];
#pragma unroll
    for (int i = 0; i < 2; i++)
#pragma unroll
        for (int j = 0; j < 8; j++)
#pragma unroll
            for (int q = 0; q < 4; q++) acc[i][j][q] = 0.f;

    uint32_t a_addr[2];
#pragma unroll
    for (int i = 0; i < 2; i++)
        a_addr[i] = sbase + AS_OFF +
                    (uint32_t)((wm + i * 16 + (lane & 15)) * WSTRIDE +
                               (lane >> 4) * 8) * 2;
    uint32_t b_addr[4];
#pragma unroll
    for (int jj = 0; jj < 4; jj++)
        b_addr[jj] = sbase + BS_OFF +
                     (uint32_t)((wn + jj * 16 + ((lane >> 4) & 1) * 8 + (lane & 7)) *
                                    WSTRIDE +
                                ((lane >> 3) & 1) * 8) * 2;

#pragma unroll
    for (int s = 0; s < 8; s++) {
        uint32_t a[2][4], b[4][4];
#pragma unroll
        for (int i = 0; i < 2; i++) ldsm4(a[i], a_addr[i] + s * 32);
#pragma unroll
        for (int jj = 0; jj < 4; jj++) ldsm4(b[jj], b_addr[jj] + s * 32);
#pragma unroll
        for (int i = 0; i < 2; i++)
#pragma unroll
            for (int jj = 0; jj < 4; jj++) {
                mma16816(acc[i][2 * jj], a[i], &b[jj][0]);
                mma16816(acc[i][2 * jj + 1], a[i], &b[jj][2]);
            }
    }
    __syncthreads();   // reuse smem as fp32 staging

    float* Cs = (float*)smem;
    int g = lane >> 2, tg = lane & 3;
#pragma unroll
    for (int i = 0; i < 2; i++) {
#pragma unroll
        for (int j = 0; j < 8; j++) {
            int col = wn + j * 8 + tg * 2;
            int r0 = wm + i * 16 + g;
            *(float2*)&Cs[r0 * CFSTR + col] = make_float2(acc[i][j][0], acc[i][j][1]);
            *(float2*)&Cs[(r0 + 8) * CFSTR + col] = make_float2(acc[i][j][2], acc[i][j][3]);
        }
    }
    __syncthreads();

#pragma unroll
    for (int it = 0; it < 16; it++) {
        int idx = it * 256 + tid;
        int r = idx >> 5, c = idx & 31;
        if (nb + r < N) {
            float4 v = *(const float4*)&Cs[r * CFSTR + c * 4];
            *(float4*)&g_gates[(size_t)(nb + r) * 256 + colbase + c * 4] = v;
        }
    }
}

// elementwise GRU update from gates; also clears g_agg for the next iteration.
__global__ void gru_elem_kernel(const float* __restrict__ b_ih,
                                const float* __restrict__ b_hh, int N) {
    int i = blockIdx.x * 256 + threadIdx.x;
    if (i >= N * DIM) return;
    int n = i >> 6, f = i & 63;
    const float* gt = g_gates + (size_t)n * 256;
    float r = 1.f / (1.f + __expf(-(gt[f] + b_ih[f] + b_hh[f])));
    float z = 1.f / (1.f + __expf(-(gt[64 + f] + b_ih[64 + f] + b_hh[64 + f])));
    float inn = gt[128 + f] + b_ih[128 + f];
    float hn  = gt[192 + f] + b_hh[128 + f];
    float ng = tanhf(inn + r * hn);
    g_h[i] = (1.f - z) * ng + z * g_h[i];
    g_agg[i] = 0.f;
}

// msg[e] = h[src[e]] @ Wedge8[e]; HFMA2 accumulation, scatter via atomics.
// v2: 32 edges/block, 8 threads/edge x 8 cols -> 1564 blocks (halved wave tail).
__global__ void __launch_bounds__(256) msg_scatter_kernel(
    const int* __restrict__ src, const int* __restrict__ dst, int E) {
    __shared__ uint32_t souts[32][68];   // half2(a,a) per d; pad 68
    __shared__ int sdst[32];
    int ty = threadIdx.x >> 3;   // edge slot 0..31
    int tx = threadIdx.x & 7;    // col group (8 cols)
    int e = blockIdx.x * 32 + ty;
    if (e < E) {
        int s = src[e];
#pragma unroll
        for (int q = 0; q < 2; q++) {
            float4 v = *(const float4*)&g_h[(size_t)s * 64 + tx * 8 + q * 4];
            __half hx = __float2half(v.x), hy = __float2half(v.y);
            __half hz = __float2half(v.z), hw = __float2half(v.w);
            __half2 d0 = __halves2half2(hx, hx);
            __half2 d1 = __halves2half2(hy, hy);
            __half2 d2 = __halves2half2(hz, hz);
            __half2 d3 = __halves2half2(hw, hw);
            souts[ty][tx * 8 + q * 4 + 0] = *(uint32_t*)&d0;
            souts[ty][tx * 8 + q * 4 + 1] = *(uint32_t*)&d1;
            souts[ty][tx * 8 + q * 4 + 2] = *(uint32_t*)&d2;
            souts[ty][tx * 8 + q * 4 + 3] = *(uint32_t*)&d3;
        }
        if (tx == 0) sdst[ty] = dst[e];
    }
    __syncthreads();
    if (e >= E) return;
    __half2 hacc[4];
#pragma unroll
    for (int j = 0; j < 4; j++) hacc[j] = __halves2half2(__ushort_as_half(0),
                                                         __ushort_as_half(0));
    const uint8_t* Wrow = g_Wedge8 + (size_t)e * 4096 + tx * 8;
#pragma unroll 8
    for (int d = 0; d < 64; d++) {
        uint32_t a2 = souts[ty][d];
        __half2 ah = *(__half2*)&a2;
        uint2 raw = *(const uint2*)(Wrow + d * 64);
        uint32_t ws[2] = {raw.x, raw.y};
#pragma unroll
        for (int q = 0; q < 2; q++) {
            uint32_t lo = e4m3x2_to_f16x2((uint16_t)ws[q]);
            uint32_t hi = e4m3x2_to_f16x2((uint16_t)(ws[q] >> 16));
            hacc[2 * q]     = __hfma2(ah, *(__half2*)&lo, hacc[2 * q]);
            hacc[2 * q + 1] = __hfma2(ah, *(__half2*)&hi, hacc[2 * q + 1]);
        }
    }
    int dn = sdst[ty];
    float* ap = g_agg + (size_t)dn * 64 + tx * 8;
#pragma unroll
    for (int j = 0; j < 4; j++) {
        float2 f = __half22float2(hacc[j]);
        atomicAdd(ap + 2 * j, f.x * WSCALE_INV);
        atomicAdd(ap + 2 * j + 1, f.y * WSCALE_INV);
    }
}

// final MLP: warp-per-edge with software-pipelined gathers.
#define FIN_EDGES 64
__global__ void __launch_bounds__(128) final_mlp_kernel(
    const float* __restrict__ ea3, const int* __restrict__ idx_a,
    const int* __restrict__ idx_b, const float* __restrict__ W_l1,
    const float* __restrict__ b_l1, const float* __restrict__ W_l2,
    const float* __restrict__ b_l2, float* __restrict__ out, int E3) {
    __shared__ float wl1[72 * 128];
    __shared__ float swl2[128];
    __shared__ float sbl1[128];
    __shared__ float feat[4][72];
    int tid = threadIdx.x;
    for (int i = tid; i < 72 * 128; i += 128) wl1[i] = W_l1[i];
    swl2[tid] = W_l2[tid];
    sbl1[tid] = b_l1[tid];
    __syncthreads();
    int w = tid >> 5, lane = tid & 31;
    float bl2v = b_l2[0];
    int base = blockIdx.x * FIN_EDGES;

    float p0 = 0.f, p1 = 0.f, p2 = 0.f, p3 = 0.f, pq = 0.f;
    {
        int e = base + w;
        if (e < E3) {
            int a = idx_a[e], b = idx_b[e];
            p0 = g_h[(size_t)a * 64 + lane];
            p1 = g_h[(size_t)b * 64 + lane];
            p2 = g_h[(size_t)a * 64 + 32 + lane];
            p3 = g_h[(size_t)b * 64 + 32 + lane];
            if (lane < 8) pq = ea3[(size_t)e * 8 + lane];
        }
    }
    for (int t = w; t < FIN_EDGES; t += 4) {
        int e = base + t;
        if (e >= E3) break;
        float n0 = 0.f, n1 = 0.f, n2 = 0.f, n3 = 0.f, nq = 0.f;
        int en = base + t + 4;
        if (t + 4 < FIN_EDGES && en < E3) {
            int a = idx_a[en], b = idx_b[en];
            n0 = g_h[(size_t)a * 64 + lane];
            n1 = g_h[(size_t)b * 64 + lane];
            n2 = g_h[(size_t)a * 64 + 32 + lane];
            n3 = g_h[(size_t)b * 64 + 32 + lane];
            if (lane < 8) nq = ea3[(size_t)en * 8 + lane];
        }
        feat[w][lane] = 0.5f * (p0 + p1);
        feat[w][32 + lane] = 0.5f * (p2 + p3);
        if (lane < 8) feat[w][64 + lane] = pq;
        __syncwarp();
        float a0 = sbl1[lane], a1 = sbl1[lane + 32],
              a2 = sbl1[lane + 64], a3 = sbl1[lane + 96];
#pragma unroll 8
        for (int i = 0; i < 72; i++) {
            float f = feat[w][i];
            a0 += f * wl1[i * 128 + lane];
            a1 += f * wl1[i * 128 + lane + 32];
            a2 += f * wl1[i * 128 + lane + 64];
            a3 += f * wl1[i * 128 + lane + 96];
        }
        float s = fmaxf(a0, 0.f) * swl2[lane] + fmaxf(a1, 0.f) * swl2[lane + 32] +
                  fmaxf(a2, 0.f) * swl2[lane + 64] + fmaxf(a3, 0.f) * swl2[lane + 96];
#pragma unroll
        for (int o = 16; o > 0; o >>= 1) s += __shfl_down_sync(0xffffffffu, s, o);
        if (lane == 0) out[e] = s + bl2v;
        __syncwarp();
        p0 = n0; p1 = n1; p2 = n2; p3 = n3; pq = nq;
    }
}

// ---------------- launch ------------------------------------------------------
extern "C" void kernel_launch(void* const* d_in, const int* in_sizes, int n_in,
                              void* d_out, int out_size) {
    const float* x          = (const float*)d_in[0];
    const float* edge_attr  = (const float*)d_in[1];
    const float* edge_attr3 = (const float*)d_in[2];
    const int*   edge_index  = (const int*)d_in[3];
    const int*   edge_index3 = (const int*)d_in[4];
    const float* W_node = (const float*)d_in[5];
    const float* b_node = (const float*)d_in[6];
    const float* W_ea   = (const float*)d_in[7];
    const float* b_ea   = (const float*)d_in[8];
    const float* W_e1   = (const float*)d_in[9];
    const float* b_e1   = (const float*)d_in[10];
    const float* W_e2   = (const float*)d_in[11];
    const float* b_e2   = (const float*)d_in[12];
    const float* conv_bias = (const float*)d_in[13];
    const float* W_ih = (const float*)d_in[14];
    const float* b_ih = (const float*)d_in[15];
    const float* W_hh = (const float*)d_in[16];
    const float* b_hh = (const float*)d_in[17];
    const float* W_l1 = (const float*)d_in[18];
    const float* b_l1 = (const float*)d_in[19];
    const float* W_l2 = (const float*)d_in[20];
    const float* b_l2 = (const float*)d_in[21];

    int N  = in_sizes[0] / 8;
    int E  = in_sizes[1] / 19;
    int E3 = in_sizes[2] / 8;
    const int* src  = edge_index;
    const int* dst  = edge_index + E;
    const int* e3a  = edge_index3;
    const int* e3b  = edge_index3 + E3;
    float* out = (float*)d_out;

    cudaFuncSetAttribute(wedge_mma_kernel,
                         cudaFuncAttributeMaxDynamicSharedMemorySize, WM_SMEM_SIZE);
    cudaFuncSetAttribute(gru_mma_kernel,
                         cudaFuncAttributeMaxDynamicSharedMemorySize, GM_SMEM_SIZE);

    // (1) node MLP + zero agg/cnt + WcatT build (fused)
    {
        int NB = (N * DIM + 255) / 256;
        prep_kernel<<<NB + 128, 256>>>(x, W_node, b_node, W_ih, W_hh, N, NB);
    }
    // (2) edge MLP (8 edges/block) + degree count + W_e2 transpose (fused)
    {
        int EB = (E + EDGES_PER_BLK - 1) / EDGES_PER_BLK;
        edge_w2t_kernel<<<EB + 4096, 128>>>(edge_attr, W_ea, b_ea, W_e1, b_e1,
                                            W_e2, dst, E);
    }
    // (3) big GEMM on tensor cores -> Wedge (e4m3*32)
    {
        dim3 grid((E + 127) / 128, 32);
        wedge_mma_kernel<<<grid, 256, WM_SMEM_SIZE>>>(b_e2, E);
    }
    // 3 conv + GRU iterations
    dim3 ggrid((N + 127) / 128, 2);
    for (int it = 0; it < 3; it++) {
        msg_scatter_kernel<<<(E + 31) / 32, 256>>>(src, dst, E);
        gru_mma_kernel<<<ggrid, 256, GM_SMEM_SIZE>>>(conv_bias, N);
        gru_elem_kernel<<<(N * DIM + 255) / 256, 256>>>(b_ih, b_hh, N);
    }
    // final pair MLP
    final_mlp_kernel<<<(E3 + FIN_EDGES - 1) / FIN_EDGES, 128>>>(
        edge_attr3, e3a, e3b, W_l1, b_l1, W_l2, b_l2, out, E3);
}